// round 1
// baseline (speedup 1.0000x reference)
#include <cuda_runtime.h>
#include <float.h>

#define NMAX 4096
#define DIM  256
#define BM   128
#define BN   128
#define BK   32

// Scratch (no device allocation allowed in kernel_launch)
__device__ int   g_posmax[NMAX];   // max d^2 over positives, float bits (init 0.0f)
__device__ int   g_negmin[NMAX];   // min d^2 over negatives, float bits (init FLT_MAX)
__device__ float g_xx[NMAX];       // squared norms
__device__ int   g_lab[NMAX];      // normalized labels

// ---------------------------------------------------------------------------
// Prep: squared norms (one warp per row), per-row reduction init,
// label dtype detection (int64 vs int32) + normalization.
// ---------------------------------------------------------------------------
__global__ void prep_kernel(const float* __restrict__ feat,
                            const int* __restrict__ lab_raw, int n) {
    int row  = blockIdx.x * 8 + (threadIdx.x >> 5);
    int lane = threadIdx.x & 31;
    if (row >= n) return;

    const float4* p = (const float4*)(feat + (long)row * DIM);
    float s = 0.f;
#pragma unroll
    for (int i = 0; i < DIM / 128; i++) {
        float4 v = p[lane + 32 * i];
        s += v.x * v.x + v.y * v.y + v.z * v.z + v.w * v.w;
    }
#pragma unroll
    for (int o = 16; o; o >>= 1) s += __shfl_xor_sync(0xffffffffu, s, o);

    if (lane == 0) {
        g_xx[row]     = s;
        g_posmax[row] = 0;                          // bits of 0.0f
        g_negmin[row] = __float_as_int(FLT_MAX);
    }
    if (lane == 1) {
        // Detect int64 labels: high 32-bit words of first 32 entries all zero.
        // (Reads stay within the first 256 bytes — valid for either dtype.)
        bool is64 = true;
#pragma unroll
        for (int i = 0; i < 32; i++)
            if (lab_raw[2 * i + 1] != 0) { is64 = false; break; }
        g_lab[row] = is64 ? lab_raw[2 * row] : lab_raw[row];
    }
}

// ---------------------------------------------------------------------------
// Fused distance-GEMM + masked row max/min epilogue.
// 128x128 tile per block, 8x8 per thread, reduction done in d^2 space.
// ---------------------------------------------------------------------------
__global__ void __launch_bounds__(256, 2)
tile_kernel(const float* __restrict__ feat, int n) {
    __shared__ float As[BK][BM];       // transposed: As[k][i]
    __shared__ float Bs[BK][BN];       // transposed: Bs[k][j]
    __shared__ int   lab_s[BM + BN];   // [0..127] row labels, [128..255] col labels

    const int bi  = blockIdx.y * BM;
    const int bj  = blockIdx.x * BN;
    const int tid = threadIdx.x;
    const int tx  = tid & 15;
    const int ty  = tid >> 4;

    // labels for this tile (first 128 threads: rows, next 128: cols)
    lab_s[tid] = (tid < BM) ? g_lab[bi + tid] : g_lab[bj + (tid - BM)];

    float acc[8][8];
#pragma unroll
    for (int r = 0; r < 8; r++)
#pragma unroll
        for (int c = 0; c < 8; c++) acc[r][c] = 0.f;

    const int row   = tid & 127;   // smem row each thread stages
    const int khalf = tid >> 7;    // 0 or 1

    for (int k0 = 0; k0 < DIM; k0 += BK) {
        __syncthreads();
        const float* arow = feat + (long)(bi + row) * DIM + k0;
        const float* brow = feat + (long)(bj + row) * DIM + k0;
#pragma unroll
        for (int s = 0; s < 4; s++) {
            int kq = khalf + 2 * s;                       // 0..7
            float4 v = *(const float4*)(arow + kq * 4);
            As[kq * 4 + 0][row] = v.x;
            As[kq * 4 + 1][row] = v.y;
            As[kq * 4 + 2][row] = v.z;
            As[kq * 4 + 3][row] = v.w;
            float4 w = *(const float4*)(brow + kq * 4);
            Bs[kq * 4 + 0][row] = w.x;
            Bs[kq * 4 + 1][row] = w.y;
            Bs[kq * 4 + 2][row] = w.z;
            Bs[kq * 4 + 3][row] = w.w;
        }
        __syncthreads();

#pragma unroll
        for (int k = 0; k < BK; k++) {
            float4 a0 = *(const float4*)&As[k][ty * 4];
            float4 a1 = *(const float4*)&As[k][64 + ty * 4];
            float4 b0 = *(const float4*)&Bs[k][tx * 4];
            float4 b1 = *(const float4*)&Bs[k][64 + tx * 4];
            float a[8] = {a0.x, a0.y, a0.z, a0.w, a1.x, a1.y, a1.z, a1.w};
            float b[8] = {b0.x, b0.y, b0.z, b0.w, b1.x, b1.y, b1.z, b1.w};
#pragma unroll
            for (int r = 0; r < 8; r++)
#pragma unroll
                for (int c = 0; c < 8; c++)
                    acc[r][c] += a[r] * b[c];
        }
    }

    // ---- Epilogue: d^2 = xx_i + xx_j - 2*dot; masked max (pos) / min (neg).
    float xj[8];
    int   lj[8];
#pragma unroll
    for (int c = 0; c < 8; c++) {
        int jl = (c < 4) ? tx * 4 + c : 64 + tx * 4 + (c - 4);
        xj[c] = g_xx[bj + jl];
        lj[c] = lab_s[128 + jl];
    }

#pragma unroll
    for (int r = 0; r < 8; r++) {
        int   il = (r < 4) ? ty * 4 + r : 64 + ty * 4 + (r - 4);
        float xi = g_xx[bi + il];
        int   li = lab_s[il];
        float posm = -1.f;       // all real d^2 (clamped later) beat this
        float negm = FLT_MAX;
#pragma unroll
        for (int c = 0; c < 8; c++) {
            float d2 = xi + xj[c] - 2.f * acc[r][c];
            if (li == lj[c]) posm = fmaxf(posm, d2);
            else             negm = fminf(negm, d2);
        }
        // reduce across the 16 lanes sharing this row (tx dimension)
#pragma unroll
        for (int o = 1; o < 16; o <<= 1) {
            posm = fmaxf(posm, __shfl_xor_sync(0xffffffffu, posm, o));
            negm = fminf(negm, __shfl_xor_sync(0xffffffffu, negm, o));
        }
        if (tx == 0) {
            // float-as-int atomics: candidates >= 0 (or negative sentinel that
            // loses to the 0-bits init); min side all >= 0 vs FLT_MAX init.
            atomicMax(&g_posmax[bi + il], __float_as_int(posm));
            atomicMin(&g_negmin[bi + il], __float_as_int(negm));
        }
    }
}

// ---------------------------------------------------------------------------
// Finalize: sqrt, validity mask, margin ranking loss mean.
// ---------------------------------------------------------------------------
__global__ void finalize_kernel(float* __restrict__ out, int n) {
    __shared__ float ss[256];
    __shared__ float sc[256];
    float sum = 0.f, cnt = 0.f;
    for (int i = threadIdx.x; i < n; i += 256) {
        float ap2 = __int_as_float(g_posmax[i]);
        float ap  = sqrtf(fmaxf(ap2, 1e-12f));       // has_pos always true (self)
        float nm2 = __int_as_float(g_negmin[i]);
        bool  has_neg = nm2 < 1e30f;
        float an  = has_neg ? sqrtf(fmaxf(nm2, 1e-12f)) : 0.f;
        bool  valid = (ap < 1000000.0f) && (an > 0.f);
        if (valid) {
            sum += fmaxf(0.3f + ap - an, 0.f);
            cnt += 1.f;
        }
    }
    ss[threadIdx.x] = sum;
    sc[threadIdx.x] = cnt;
    __syncthreads();
    for (int o = 128; o; o >>= 1) {
        if (threadIdx.x < o) {
            ss[threadIdx.x] += ss[threadIdx.x + o];
            sc[threadIdx.x] += sc[threadIdx.x + o];
        }
        __syncthreads();
    }
    if (threadIdx.x == 0)
        out[0] = (sc[0] > 0.f) ? ss[0] / fmaxf(sc[0], 1.f) : 0.f;
}

// ---------------------------------------------------------------------------
extern "C" void kernel_launch(void* const* d_in, const int* in_sizes, int n_in,
                              void* d_out, int out_size) {
    const float* feat   = (const float*)d_in[0];
    const int*   labels = (const int*)d_in[1];   // int32 or int64 — auto-detected
    int n = in_sizes[1];                         // 4096

    prep_kernel<<<(n + 7) / 8, 256>>>(feat, labels, n);

    dim3 grid(n / BN, n / BM);                   // 32 x 32 = 1024 blocks
    tile_kernel<<<grid, 256>>>(feat, n);

    finalize_kernel<<<1, 256>>>((float*)d_out, n);
}

// round 3
// speedup vs baseline: 2.3534x; 2.3534x over previous
#include <cuda_runtime.h>
#include <cuda_bf16.h>
#include <float.h>
#include <stdint.h>

#define NMAX 4096
#define DIMK 256              // fp32 features per row
#define KC   64               // bf16 elements per K-chunk (128 bytes per row)
#define NCH  (DIMK / KC)      // 4 chunks

// ---------------- device scratch (no allocs allowed) ----------------
__device__ int   g_posmax[NMAX];                 // max d^2 over positives, float bits
__device__ int   g_negmin[NMAX];                 // min d^2 over negatives, float bits
__device__ float g_xx[NMAX];                     // squared norms
__device__ int   g_lab[NMAX];                    // normalized labels
__device__ __align__(16) __nv_bfloat16 g_hi[NMAX * DIMK];
__device__ __align__(16) __nv_bfloat16 g_lo[NMAX * DIMK];

// ---------------- baseline-ISA PTX helpers (sm_80+, no 'a' features) --------
__device__ __forceinline__ uint32_t s2u(const void* p) {
    uint32_t a;
    asm("{ .reg .u64 t; cvta.to.shared.u64 t, %1; cvt.u32.u64 %0, t; }" : "=r"(a) : "l"(p));
    return a;
}
__device__ __forceinline__ void cp16(uint32_t saddr, const void* g) {
    asm volatile("cp.async.cg.shared.global [%0], [%1], 16;" :: "r"(saddr), "l"(g) : "memory");
}
#define CP_COMMIT() asm volatile("cp.async.commit_group;" ::: "memory")
template <int N> __device__ __forceinline__ void cp_wait() {
    asm volatile("cp.async.wait_group %0;" :: "n"(N) : "memory");
}
__device__ __forceinline__ void ldsm4(uint32_t* r, uint32_t a) {
    asm volatile("ldmatrix.sync.aligned.m8n8.x4.shared.b16 {%0,%1,%2,%3}, [%4];"
                 : "=r"(r[0]), "=r"(r[1]), "=r"(r[2]), "=r"(r[3]) : "r"(a));
}
__device__ __forceinline__ void mma16816(float* d, const uint32_t* a, const uint32_t* b) {
    asm volatile(
        "mma.sync.aligned.m16n8k16.row.col.f32.bf16.bf16.f32 "
        "{%0,%1,%2,%3}, {%4,%5,%6,%7}, {%8,%9}, {%0,%1,%2,%3};"
        : "+f"(d[0]), "+f"(d[1]), "+f"(d[2]), "+f"(d[3])
        : "r"(a[0]), "r"(a[1]), "r"(a[2]), "r"(a[3]), "r"(b[0]), "r"(b[1]));
}
#define SWZ(x) ((x) ^ ((((uint32_t)(x)) >> 3) & 0x70))

// SMEM layout (relative to 128-aligned base)
#define SM_LABI  0            // 128 int
#define SM_XXI   512          // 128 float
#define SM_LABJ  1024
#define SM_XXJ   1536
#define SM_STAGE 2048         // 2 stages x 64KB, 4 components of 16KB each
#define STAGE_SZ 65536
#define COMP_SZ  16384
#define SMEM_TOTAL (SM_STAGE + 2 * STAGE_SZ + 128)

// ---------------------------------------------------------------------------
// Prep: bf16 hi/lo split, squared norms, label normalization, init.
// ---------------------------------------------------------------------------
__global__ void prep_kernel(const float* __restrict__ feat,
                            const int* __restrict__ lab_raw, int n) {
    int row  = blockIdx.x * 8 + (threadIdx.x >> 5);
    int lane = threadIdx.x & 31;
    if (row >= n) return;

    const float4* p = (const float4*)(feat + (size_t)row * DIMK);
    float s = 0.f;
#pragma unroll
    for (int i = 0; i < 2; i++) {
        float4 v = p[lane + 32 * i];
        s += v.x * v.x + v.y * v.y + v.z * v.z + v.w * v.w;
        __nv_bfloat16 hx = __float2bfloat16(v.x), hy = __float2bfloat16(v.y);
        __nv_bfloat16 hz = __float2bfloat16(v.z), hw = __float2bfloat16(v.w);
        int base = row * DIMK + (lane + 32 * i) * 4;
        __nv_bfloat162* H = (__nv_bfloat162*)(g_hi + base);
        __nv_bfloat162 h0; h0.x = hx; h0.y = hy;
        __nv_bfloat162 h1; h1.x = hz; h1.y = hw;
        H[0] = h0; H[1] = h1;
        __nv_bfloat162* L = (__nv_bfloat162*)(g_lo + base);
        __nv_bfloat162 l0, l1;
        l0.x = __float2bfloat16(v.x - __bfloat162float(hx));
        l0.y = __float2bfloat16(v.y - __bfloat162float(hy));
        l1.x = __float2bfloat16(v.z - __bfloat162float(hz));
        l1.y = __float2bfloat16(v.w - __bfloat162float(hw));
        L[0] = l0; L[1] = l1;
    }
#pragma unroll
    for (int o = 16; o; o >>= 1) s += __shfl_xor_sync(0xffffffffu, s, o);

    if (lane == 0) {
        g_xx[row]     = s;
        g_posmax[row] = 0;                       // bits of +0.0f
        g_negmin[row] = __float_as_int(FLT_MAX);
    }
    if (lane == 1) {
        bool is64 = true;
#pragma unroll
        for (int i = 0; i < 32; i++)
            if (lab_raw[2 * i + 1] != 0) { is64 = false; break; }
        g_lab[row] = is64 ? lab_raw[2 * row] : lab_raw[row];
    }
}

// ---------------------------------------------------------------------------
// Load one 64-wide K chunk (4 components x 128 rows x 128B, SW128 swizzled)
// ---------------------------------------------------------------------------
__device__ __forceinline__ void load_chunk(uint32_t stage, int bi, int bj,
                                           int c, int tid) {
    const int row  = tid & 127;
    const int half = tid >> 7;       // 0/1: which 64B half of the row
    const size_t ga = (size_t)(bi + row) * DIMK + c * KC;
    const size_t gb = (size_t)(bj + row) * DIMK + c * KC;
    const char* Ah = (const char*)(g_hi + ga);
    const char* Al = (const char*)(g_lo + ga);
    const char* Bh = (const char*)(g_hi + gb);
    const char* Bl = (const char*)(g_lo + gb);
    const uint32_t ro = (uint32_t)row * 128;
#pragma unroll
    for (int q = 0; q < 4; q++) {
        uint32_t off = half * 64 + q * 16;
        uint32_t so  = SWZ(ro + off);
        cp16(stage + 0 * COMP_SZ + so, Ah + off);
        cp16(stage + 1 * COMP_SZ + so, Al + off);
        cp16(stage + 2 * COMP_SZ + so, Bh + off);
        cp16(stage + 3 * COMP_SZ + so, Bl + off);
    }
}

// ---------------------------------------------------------------------------
// MMA over one chunk: acc += Ah*Bh^T + Ah*Bl^T + Al*Bh^T  (per-warp 32x64)
// ---------------------------------------------------------------------------
__device__ __forceinline__ void mma_chunk_w(float acc[2][8][4], uint32_t st,
                                            int m_base, int n_base, int lane) {
    const uint32_t sAh = st, sAl = st + COMP_SZ;
    const uint32_t sBh = st + 2 * COMP_SZ, sBl = st + 3 * COMP_SZ;
#pragma unroll
    for (int s = 0; s < 4; s++) {                 // k16 steps within KC=64
        const uint32_t koff = (uint32_t)s * 32 + ((lane >> 4) << 4);
        uint32_t ah[2][4], al[2][4], bh[4][4], bl[4][4];
#pragma unroll
        for (int mt = 0; mt < 2; mt++) {
            uint32_t ad = SWZ((uint32_t)(m_base + mt * 16 + (lane & 15)) * 128 + koff);
            ldsm4(ah[mt], sAh + ad);
            ldsm4(al[mt], sAl + ad);
        }
#pragma unroll
        for (int p = 0; p < 4; p++) {             // each x4 covers 2 n-tiles
            uint32_t bd = SWZ((uint32_t)(n_base + p * 16 + (lane & 15)) * 128 + koff);
            ldsm4(bh[p], sBh + bd);
            ldsm4(bl[p], sBl + bd);
        }
#pragma unroll
        for (int mt = 0; mt < 2; mt++)
#pragma unroll
            for (int nt = 0; nt < 8; nt++) {
                const int p = nt >> 1, q = nt & 1;
                uint32_t bH[2] = {bh[p][q], bh[p][2 + q]};
                uint32_t bL[2] = {bl[p][q], bl[p][2 + q]};
                mma16816(acc[mt][nt], ah[mt], bH);   // hi*hi
                mma16816(acc[mt][nt], ah[mt], bL);   // hi*lo
                mma16816(acc[mt][nt], al[mt], bH);   // lo*hi
            }
    }
}

// ---------------------------------------------------------------------------
// Persistent upper-triangle tile kernel with dual-direction epilogue.
// ---------------------------------------------------------------------------
__global__ void __launch_bounds__(256, 1) tile_kernel(int n) {
    extern __shared__ char smem_raw[];
    uint32_t sb_raw = s2u(smem_raw);
    uint32_t pad = (128u - (sb_raw & 127u)) & 127u;
    char* sm = smem_raw + pad;
    uint32_t sb = sb_raw + pad;

    int*   labi = (int*)(sm + SM_LABI);
    float* xxi  = (float*)(sm + SM_XXI);
    int*   labj = (int*)(sm + SM_LABJ);
    float* xxj  = (float*)(sm + SM_XXJ);

    const int tid = threadIdx.x, lane = tid & 31, w = tid >> 5;
    const int m_base = (w & 3) * 32;     // 4 warps along M
    const int n_base = (w >> 2) * 64;    // 2 warps along N

    const int ntb = n >> 7;
    const int T   = ntb * (ntb + 1) / 2; // upper triangle incl. diagonal

    for (int t = blockIdx.x; t < T; t += gridDim.x) {
        int ti = 0, rem = t;
        while (rem >= ntb - ti) { rem -= ntb - ti; ti++; }
        const int tj = ti + rem;
        const int bi = ti << 7, bj = tj << 7;

        __syncthreads();                  // smem reuse guard vs prev epilogue
        if (tid < 128) { labi[tid] = g_lab[bi + tid]; xxi[tid] = g_xx[bi + tid]; }
        else { labj[tid - 128] = g_lab[bj + tid - 128]; xxj[tid - 128] = g_xx[bj + tid - 128]; }

        float acc[2][8][4];
#pragma unroll
        for (int a = 0; a < 2; a++)
#pragma unroll
            for (int b = 0; b < 8; b++)
#pragma unroll
                for (int e = 0; e < 4; e++) acc[a][b][e] = 0.f;

        load_chunk(sb + SM_STAGE, bi, bj, 0, tid);
        CP_COMMIT();
#pragma unroll
        for (int c = 0; c < NCH; c++) {
            if (c + 1 < NCH) {
                load_chunk(sb + SM_STAGE + ((c + 1) & 1) * STAGE_SZ, bi, bj, c + 1, tid);
                CP_COMMIT();
                cp_wait<1>();
            } else {
                cp_wait<0>();
            }
            __syncthreads();              // chunk c visible to all warps
            mma_chunk_w(acc, sb + SM_STAGE + (c & 1) * STAGE_SZ, m_base, n_base, lane);
            __syncthreads();              // stage free for overwrite
        }

        // ---- epilogue: d^2 in-place, then row + column masked reductions ----
        float xi[4]; int li[4];
#pragma unroll
        for (int mt = 0; mt < 2; mt++)
#pragma unroll
            for (int rh = 0; rh < 2; rh++) {
                int r = m_base + mt * 16 + (lane >> 2) + 8 * rh;
                xi[mt * 2 + rh] = xxi[r];
                li[mt * 2 + rh] = labi[r];
            }
        float xj[16]; int lj[16];
#pragma unroll
        for (int nt = 0; nt < 8; nt++)
#pragma unroll
            for (int cc = 0; cc < 2; cc++) {
                int cidx = n_base + nt * 8 + (lane & 3) * 2 + cc;
                xj[nt * 2 + cc] = xxj[cidx];
                lj[nt * 2 + cc] = labj[cidx];
            }
#pragma unroll
        for (int mt = 0; mt < 2; mt++)
#pragma unroll
            for (int nt = 0; nt < 8; nt++)
#pragma unroll
                for (int e = 0; e < 4; e++) {
                    int rh = e >> 1, cc = e & 1;
                    acc[mt][nt][e] = fmaf(-2.f, acc[mt][nt][e],
                                          xi[mt * 2 + rh] + xj[nt * 2 + cc]);
                }

        // row direction: rows of block bi vs cols of block bj
#pragma unroll
        for (int mt = 0; mt < 2; mt++)
#pragma unroll
            for (int rh = 0; rh < 2; rh++) {
                float pm = -1.f, nm = FLT_MAX;
                const int L = li[mt * 2 + rh];
#pragma unroll
                for (int nt = 0; nt < 8; nt++)
#pragma unroll
                    for (int cc = 0; cc < 2; cc++) {
                        float v = acc[mt][nt][rh * 2 + cc];
                        if (L == lj[nt * 2 + cc]) pm = fmaxf(pm, v);
                        else                      nm = fminf(nm, v);
                    }
                pm = fmaxf(pm, __shfl_xor_sync(0xffffffffu, pm, 1));
                pm = fmaxf(pm, __shfl_xor_sync(0xffffffffu, pm, 2));
                nm = fminf(nm, __shfl_xor_sync(0xffffffffu, nm, 1));
                nm = fminf(nm, __shfl_xor_sync(0xffffffffu, nm, 2));
                if ((lane & 3) == 0) {
                    int gi = bi + m_base + mt * 16 + (lane >> 2) + 8 * rh;
                    atomicMax(&g_posmax[gi], __float_as_int(pm));
                    atomicMin(&g_negmin[gi], __float_as_int(nm));
                }
            }

        // column direction (symmetry): rows of block bj vs cols of block bi
#pragma unroll
        for (int nt = 0; nt < 8; nt++)
#pragma unroll
            for (int cc = 0; cc < 2; cc++) {
                float pm = -1.f, nm = FLT_MAX;
                const int L = lj[nt * 2 + cc];
#pragma unroll
                for (int mt = 0; mt < 2; mt++)
#pragma unroll
                    for (int rh = 0; rh < 2; rh++) {
                        float v = acc[mt][nt][rh * 2 + cc];
                        if (L == li[mt * 2 + rh]) pm = fmaxf(pm, v);
                        else                      nm = fminf(nm, v);
                    }
                pm = fmaxf(pm, __shfl_xor_sync(0xffffffffu, pm, 4));
                pm = fmaxf(pm, __shfl_xor_sync(0xffffffffu, pm, 8));
                pm = fmaxf(pm, __shfl_xor_sync(0xffffffffu, pm, 16));
                nm = fminf(nm, __shfl_xor_sync(0xffffffffu, nm, 4));
                nm = fminf(nm, __shfl_xor_sync(0xffffffffu, nm, 8));
                nm = fminf(nm, __shfl_xor_sync(0xffffffffu, nm, 16));
                if (lane < 4) {
                    int gj = bj + n_base + nt * 8 + (lane & 3) * 2 + cc;
                    atomicMax(&g_posmax[gj], __float_as_int(pm));
                    atomicMin(&g_negmin[gj], __float_as_int(nm));
                }
            }
    }
}

// ---------------------------------------------------------------------------
// Finalize: sqrt, validity, margin ranking loss mean.
// ---------------------------------------------------------------------------
__global__ void finalize_kernel(float* __restrict__ out, int n) {
    __shared__ float ss[256];
    __shared__ float sc[256];
    float sum = 0.f, cnt = 0.f;
    for (int i = threadIdx.x; i < n; i += 256) {
        float ap2 = __int_as_float(g_posmax[i]);
        float ap  = sqrtf(fmaxf(ap2, 1e-12f));
        float nm2 = __int_as_float(g_negmin[i]);
        bool  has_neg = nm2 < 1e30f;
        float an  = has_neg ? sqrtf(fmaxf(nm2, 1e-12f)) : 0.f;
        bool  valid = (ap < 1000000.0f) && (an > 0.f);
        if (valid) {
            sum += fmaxf(0.3f + ap - an, 0.f);
            cnt += 1.f;
        }
    }
    ss[threadIdx.x] = sum;
    sc[threadIdx.x] = cnt;
    __syncthreads();
    for (int o = 128; o; o >>= 1) {
        if (threadIdx.x < o) {
            ss[threadIdx.x] += ss[threadIdx.x + o];
            sc[threadIdx.x] += sc[threadIdx.x + o];
        }
        __syncthreads();
    }
    if (threadIdx.x == 0)
        out[0] = (sc[0] > 0.f) ? ss[0] / fmaxf(sc[0], 1.f) : 0.f;
}

// ---------------------------------------------------------------------------
extern "C" void kernel_launch(void* const* d_in, const int* in_sizes, int n_in,
                              void* d_out, int out_size) {
    const float* feat   = (const float*)d_in[0];
    const int*   labels = (const int*)d_in[1];   // int32/int64 auto-detected
    int n = in_sizes[1];                         // 4096

    cudaFuncSetAttribute(tile_kernel, cudaFuncAttributeMaxDynamicSharedMemorySize,
                         SMEM_TOTAL);

    prep_kernel<<<(n + 7) / 8, 256>>>(feat, labels, n);
    tile_kernel<<<148, 256, SMEM_TOTAL>>>(n);
    finalize_kernel<<<1, 256>>>((float*)d_out, n);
}